// round 9
// baseline (speedup 1.0000x reference)
#include <cuda_runtime.h>
#include <cuda_fp16.h>
#include <mma.h>
#include <math.h>

using namespace nvcuda;

// ---------------- problem constants ----------------
#define Lc   2
#define Dc   4096
#define KVc  1024
#define Fc   14336
#define Hc   32
#define HKc  8
#define HDc  128
#define Bc   2
#define Sc   1024
#define Mc   (Bc*Sc)     // 2048 rows
#define BHc  (Bc*Hc)     // 64 attention batches
#define RMS_EPS 1e-5f

// idx array sizes (elements) per layer
#define SQe  (Dc*Dc)            // 16777216
#define SKVe (KVc*Dc)           // 4194304
#define SFe  (Fc*Dc)            // 58720256
#define TLe  (2*SQe + 2*SKVe + 3*SFe)   // 218103808 per layer
// canonical offsets within a layer
#define OQ 0
#define OK (SQe)
#define OV (SQe + SKVe)
#define OO (SQe + 2*SKVe)
#define OG (2*SQe + 2*SKVe)
#define OU (2*SQe + 2*SKVe + SFe)
#define OD (2*SQe + 2*SKVe + 2*SFe)

// ---------------- scratch (device globals; allocation-free) ----------------
__device__ float   g_h[Mc*Dc];                       // residual stream (f32)
__device__ __half  g_x[Mc*Dc];                       // normed activations (fp16)
__device__ float   g_q[Mc*Dc];                       // q f32   (aliased later as ctx f32)
__device__ float   g_k[Mc*KVc];                      // k f32
__device__ float   g_v[Mc*KVc];                      // v f32
__device__ __half  g_qh[Mc*Dc];                      // q fp16 (post-rope)
__device__ __half  g_kh[Mc*Dc];                      // k fp16 (post-rope, GQA-expanded)
__device__ __half  g_vh[Mc*Dc];                      // v fp16 (GQA-expanded)
__device__ float   g_scores[(size_t)BHc*Sc*Sc];      // 268MB (aliased as MLP gate f32)
__device__ __half  g_probs[(size_t)BHc*Sc*Sc];       // 134MB (aliased as MLP up f32)
__device__ __half  g_ctxh[Mc*Dc];                    // ctx fp16
__device__ __half  g_act[Mc*Fc];                     // silu(g)*u fp16
__device__ float   g_cos[Sc*64];
__device__ float   g_sin[Sc*64];
__device__ float   g_rms[Mc];                        // final-ln scales
__device__ unsigned char g_wq8[(size_t)Lc*TLe];      // canonical uint8 NF4 codes (416MB)
__device__ int     g_idx_mode;                       // 0=uint8, 1=int32, 2=float32

__constant__ float NF4[16] = {
    -1.0f, -0.6961928009986877f, -0.5250730514526367f, -0.39491748809814453f,
    -0.28444138169288635f, -0.18477343022823334f, -0.09105003625154495f, 0.0f,
    0.07958029955625534f, 0.16093020141124725f, 0.24611230194568634f,
    0.33791524171829224f, 0.44070982933044434f, 0.5626170039176941f,
    0.7229568362236023f, 1.0f };

// ---------------- idx dtype detection + normalization ----------------
// The harness may deliver the uint8 NF4 code arrays promoted to int32 or
// float32 (its documented dtype set is f32/i32/bf16). Detect the layout from
// the first 64 words of q_idx and normalize everything to uint8.
__global__ void detect_k(const void* qidx) {
    if (threadIdx.x != 0 || blockIdx.x != 0) return;
    const unsigned int* w = (const unsigned int*)qidx;
    bool all_i32 = true, all_f32 = true;
    for (int i = 0; i < 64; i++) {
        unsigned int v = w[i];
        if (v >= 16u) all_i32 = false;
        float f = __uint_as_float(v);
        if (!(f >= 0.f && f < 16.f && f == floorf(f))) all_f32 = false;
    }
    // genuine uint8 random codes make both patterns (bytes 1-3 all zero /
    // valid small-int float bit patterns) probabilistically impossible.
    g_idx_mode = all_i32 ? 1 : (all_f32 ? 2 : 0);
}

__global__ void conv_idx_k(const void* __restrict__ src, size_t elem_off,
                           unsigned char* __restrict__ dst, int n4) {
    int t = blockIdx.x * 256 + threadIdx.x;            // 4 codes per thread
    if (t >= n4) return;
    const int mode = g_idx_mode;
    size_t e4 = (elem_off >> 2) + (size_t)t;           // elem_off % 4 == 0 always
    uchar4 o;
    if (mode == 0) {
        o = ((const uchar4*)src)[e4];
    } else if (mode == 1) {
        int4 v = ((const int4*)src)[e4];
        o = make_uchar4((unsigned char)v.x, (unsigned char)v.y,
                        (unsigned char)v.z, (unsigned char)v.w);
    } else {
        float4 v = ((const float4*)src)[e4];
        o = make_uchar4((unsigned char)(int)v.x, (unsigned char)(int)v.y,
                        (unsigned char)(int)v.z, (unsigned char)(int)v.w);
    }
    ((uchar4*)dst)[t] = o;
}

// ---------------- elementwise kernels ----------------
__global__ void embed_k(const int* __restrict__ ids, const float* __restrict__ emb) {
    int t = blockIdx.x * 256 + threadIdx.x;           // over Mc*Dc/4
    if (t >= Mc*Dc/4) return;
    int row = t / (Dc/4);
    int c4  = t % (Dc/4);
    ((float4*)g_h)[t] = ((const float4*)(emb + (size_t)ids[row]*Dc))[c4];
}

__global__ void rope_table_k() {
    int t = blockIdx.x * 256 + threadIdx.x;
    if (t >= Sc*64) return;
    int s = t >> 6, j = t & 63;
    double inv = pow(500000.0, -(double)(2*j) / 128.0);
    float ang = (float)s * (float)inv;
    g_cos[t] = cosf(ang);
    g_sin[t] = sinf(ang);
}

__global__ void rmsnorm_k(const float* __restrict__ src, const float* __restrict__ w,
                          __half* __restrict__ dst) {
    int row = blockIdx.x;
    const float* x = src + (size_t)row*Dc;
    __half* y = dst + (size_t)row*Dc;
    int tid = threadIdx.x;
    float s = 0.f;
    for (int d = tid*4; d < Dc; d += 1024) {
        float4 v = *(const float4*)(x + d);
        s += v.x*v.x + v.y*v.y + v.z*v.z + v.w*v.w;
    }
    __shared__ float red[256];
    red[tid] = s; __syncthreads();
    for (int o = 128; o > 0; o >>= 1) { if (tid < o) red[tid] += red[tid+o]; __syncthreads(); }
    float r = rsqrtf(red[0] / (float)Dc + RMS_EPS);
    for (int d = tid; d < Dc; d += 256) y[d] = __float2half(x[d] * r * w[d]);
}

__global__ void rms_scale_k(const float* __restrict__ src) {
    int row = blockIdx.x;
    const float* x = src + (size_t)row*Dc;
    int tid = threadIdx.x;
    float s = 0.f;
    for (int d = tid*4; d < Dc; d += 1024) {
        float4 v = *(const float4*)(x + d);
        s += v.x*v.x + v.y*v.y + v.z*v.z + v.w*v.w;
    }
    __shared__ float red[256];
    red[tid] = s; __syncthreads();
    for (int o = 128; o > 0; o >>= 1) { if (tid < o) red[tid] += red[tid+o]; __syncthreads(); }
    if (tid == 0) g_rms[row] = rsqrtf(red[0] / (float)Dc + RMS_EPS);
}

__global__ void rope_q_k() {
    int t = blockIdx.x * 256 + threadIdx.x;           // over Mc*Hc*64
    if (t >= Mc*Hc*64) return;
    int j  = t & 63;
    int bh = t >> 6;
    int hh = bh % Hc;
    int bs = bh / Hc;
    int s  = bs % Sc;
    size_t base = (size_t)bs*Dc + (size_t)hh*HDc;
    float x1 = g_q[base + j], x2 = g_q[base + 64 + j];
    float c = g_cos[s*64 + j], sn = g_sin[s*64 + j];
    g_qh[base + j]      = __float2half(x1*c - x2*sn);
    g_qh[base + 64 + j] = __float2half(x2*c + x1*sn);
}

__global__ void rope_k_k() {
    int t = blockIdx.x * 256 + threadIdx.x;           // over Mc*Hc*64 (GQA expand)
    if (t >= Mc*Hc*64) return;
    int j  = t & 63;
    int bh = t >> 6;
    int hh = bh % Hc;
    int bs = bh / Hc;
    int s  = bs % Sc;
    size_t src = (size_t)bs*KVc + (size_t)(hh >> 2)*HDc;
    size_t dst = (size_t)bs*Dc  + (size_t)hh*HDc;
    float x1 = g_k[src + j], x2 = g_k[src + 64 + j];
    float c = g_cos[s*64 + j], sn = g_sin[s*64 + j];
    g_kh[dst + j]      = __float2half(x1*c - x2*sn);
    g_kh[dst + 64 + j] = __float2half(x2*c + x1*sn);
}

__global__ void conv_v_k() {
    int t = blockIdx.x * 256 + threadIdx.x;           // over Mc*Dc  (GQA expand)
    if (t >= Mc*Dc) return;
    int d    = t & 127;
    int rest = t >> 7;
    int hh   = rest % Hc;
    int bs   = rest / Hc;
    g_vh[t] = __float2half(g_v[(size_t)bs*KVc + (size_t)(hh >> 2)*HDc + d]);
}

__global__ void f2h_k(const float* __restrict__ src, __half* __restrict__ dst, int n) {
    int t = blockIdx.x * 256 + threadIdx.x;
    if (t < n) dst[t] = __float2half(src[t]);
}

__global__ void silu_k(const float* __restrict__ g, const float* __restrict__ u,
                       __half* __restrict__ act, int n) {
    int t = blockIdx.x * 256 + threadIdx.x;
    if (t >= n) return;
    float gv = g[t];
    act[t] = __float2half(gv / (1.f + __expf(-gv)) * u[t]);
}

__global__ void softmax_k(const int* __restrict__ am,
                          const float* __restrict__ scores, __half* __restrict__ probs) {
    const int z  = blockIdx.x;                        // bh*Sc + i
    const int i  = z % Sc;
    const int bh = z / Sc;
    const int b  = bh / Hc;
    const float* row = scores + (size_t)bh*Sc*Sc + (size_t)i*Sc;
    __half* prow     = probs  + (size_t)bh*Sc*Sc + (size_t)i*Sc;
    const int tid = threadIdx.x;
    const float scale = 0.08838834764831845f;         // 1/sqrt(128)
    __shared__ float red[256];
    float mx = -3.4e38f;
    for (int j = tid; j < Sc; j += 256) {
        bool valid = (j <= i) && (am[b*Sc + j] > 0);
        if (valid) mx = fmaxf(mx, row[j] * scale);
    }
    red[tid] = mx; __syncthreads();
    for (int o = 128; o > 0; o >>= 1) { if (tid < o) red[tid] = fmaxf(red[tid], red[tid+o]); __syncthreads(); }
    mx = red[0]; __syncthreads();
    float sum = 0.f;
    for (int j = tid; j < Sc; j += 256) {
        bool valid = (j <= i) && (am[b*Sc + j] > 0);
        if (valid) sum += __expf(row[j] * scale - mx);
    }
    red[tid] = sum; __syncthreads();
    for (int o = 128; o > 0; o >>= 1) { if (tid < o) red[tid] += red[tid+o]; __syncthreads(); }
    float inv = 1.f / red[0];
    for (int j = tid; j < Sc; j += 256) {
        bool valid = (j <= i) && (am[b*Sc + j] > 0);
        float e = valid ? __expf(row[j] * scale - mx) * inv : 0.f;
        prow[j] = __float2half(e);
    }
}

__global__ void pool_k(const int* __restrict__ am, const float* __restrict__ w,
                       float* __restrict__ out) {
    int t = blockIdx.x * 256 + threadIdx.x;           // over Bc*Dc
    if (t >= Bc*Dc) return;
    int b = t / Dc, d = t % Dc;
    float acc = 0.f, cnt = 0.f;
    #pragma unroll 4
    for (int s = 0; s < Sc; s++) {
        float m = (float)am[b*Sc + s];
        acc += g_h[((size_t)(b*Sc + s))*Dc + d] * g_rms[b*Sc + s] * m;
        cnt += m;
    }
    out[t] = acc * w[d] / fmaxf(cnt, 1e-9f);
}

// ---------------- tensor-core GEMM (fp16 B operand; attention path) ----------
// C[M,N] = A[M,K] @ op(B)  (+ C if ACC)
//   BT=true : B stored (N,K) row-major  -> C = A @ B^T
//   BT=false: B stored (K,N) row-major  -> C = A @ B
// Batched via grid.z with offset = (z/zdiv)*s1 + (z%zdiv)*s2 per operand.
template<bool BT, bool ACC>
__global__ void __launch_bounds__(256) gemm_tc(
    const __half* __restrict__ A, const __half* __restrict__ B, float* __restrict__ C,
    int K, int lda, int ldb, int ldc,
    long long a1, long long a2, long long b1, long long b2,
    long long c1, long long c2, int zdiv)
{
    const int z = blockIdx.z;
    const long long zq = z / zdiv, zr = z % zdiv;
    A += zq*a1 + zr*a2;
    B += zq*b1 + zr*b2;
    C += zq*c1 + zr*c2;
    const int m0 = blockIdx.y * 128, n0 = blockIdx.x * 128;

    __shared__ __half sA[128][48];
    constexpr int SBR = BT ? 128 : 32;
    constexpr int SBC = BT ? 48 : 136;
    __shared__ __half sB[SBR][SBC];

    const int tid  = threadIdx.x;
    const int warp = tid >> 5;
    const int wm   = warp & 3;          // 4 warps along M
    const int wn   = warp >> 2;         // 2 warps along N

    wmma::fragment<wmma::accumulator,16,16,16,float> acc[2][4];
    #pragma unroll
    for (int i = 0; i < 2; i++)
        #pragma unroll
        for (int j = 0; j < 4; j++) wmma::fill_fragment(acc[i][j], 0.f);

    for (int k0 = 0; k0 < K; k0 += 32) {
        #pragma unroll
        for (int i = 0; i < 2; i++) {
            int v = tid + i*256;
            int r = v >> 2, c = (v & 3) * 8;
            *(uint4*)&sA[r][c] = *(const uint4*)(A + (long long)(m0 + r)*lda + (k0 + c));
        }
        if constexpr (BT) {
            #pragma unroll
            for (int i = 0; i < 2; i++) {
                int v = tid + i*256;
                int r = v >> 2, c = (v & 3) * 8;
                *(uint4*)&sB[r][c] = *(const uint4*)(B + (long long)(n0 + r)*ldb + (k0 + c));
            }
        } else {
            #pragma unroll
            for (int i = 0; i < 2; i++) {
                int v = tid + i*256;
                int r = v >> 4, c = (v & 15) * 8;
                *(uint4*)&sB[r][c] = *(const uint4*)(B + (long long)(k0 + r)*ldb + (n0 + c));
            }
        }
        __syncthreads();

        #pragma unroll
        for (int kk = 0; kk < 32; kk += 16) {
            wmma::fragment<wmma::matrix_a,16,16,16,__half,wmma::row_major> af[2];
            #pragma unroll
            for (int i = 0; i < 2; i++)
                wmma::load_matrix_sync(af[i], &sA[wm*32 + i*16][kk], 48);
            if constexpr (BT) {
                #pragma unroll
                for (int j = 0; j < 4; j++) {
                    wmma::fragment<wmma::matrix_b,16,16,16,__half,wmma::col_major> bf;
                    wmma::load_matrix_sync(bf, &sB[wn*64 + j*16][kk], 48);
                    #pragma unroll
                    for (int i = 0; i < 2; i++) wmma::mma_sync(acc[i][j], af[i], bf, acc[i][j]);
                }
            } else {
                #pragma unroll
                for (int j = 0; j < 4; j++) {
                    wmma::fragment<wmma::matrix_b,16,16,16,__half,wmma::row_major> bf;
                    wmma::load_matrix_sync(bf, &sB[kk][wn*64 + j*16], 136);
                    #pragma unroll
                    for (int i = 0; i < 2; i++) wmma::mma_sync(acc[i][j], af[i], bf, acc[i][j]);
                }
            }
        }
        __syncthreads();
    }

    #pragma unroll
    for (int i = 0; i < 2; i++)
        #pragma unroll
        for (int j = 0; j < 4; j++) {
            float* cp = C + (long long)(m0 + wm*32 + i*16)*ldc + (n0 + wn*64 + j*16);
            if constexpr (ACC) {
                wmma::fragment<wmma::accumulator,16,16,16,float> cf;
                wmma::load_matrix_sync(cf, cp, ldc, wmma::mem_row_major);
                #pragma unroll
                for (int e = 0; e < cf.num_elements; e++) acc[i][j].x[e] += cf.x[e];
            }
            wmma::store_matrix_sync(cp, acc[i][j], ldc, wmma::mem_row_major);
        }
}

// ---------------- fused NF4-dequant tensor-core GEMM (projection path) ------
// C[M,N] = A[M,K] @ Wq^T  (+ C if ACC), Wq: canonical uint8 codes (N,K)
// row-major, Bamax[(n*K + k)/64] block scales. Double-buffered; numerically
// identical to standalone dequant (fp32 NF4[c]*amax, round-to-nearest half).
template<bool ACC>
__global__ void __launch_bounds__(256) gemm_qt(
    const __half* __restrict__ A,
    const unsigned char* __restrict__ Bq,
    const float* __restrict__ Bamax,
    float* __restrict__ C,
    int K, int lda, int ldc)
{
    const int m0 = blockIdx.y * 128, n0 = blockIdx.x * 128;

    __shared__ __half sA[2][128][48];
    __shared__ __half sB[2][128][48];

    const int tid  = threadIdx.x;
    const int warp = tid >> 5;
    const int wm   = warp & 3;
    const int wn   = warp >> 2;

    const int r0 = tid >> 2,               c0 = (tid & 3) * 8;
    const int r1 = (tid + 256) >> 2,       c1 = ((tid + 256) & 3) * 8;

    wmma::fragment<wmma::accumulator,16,16,16,float> acc[2][4];
    #pragma unroll
    for (int i = 0; i < 2; i++)
        #pragma unroll
        for (int j = 0; j < 4; j++) wmma::fill_fragment(acc[i][j], 0.f);

    const int NT = K >> 5;
    uint4 ra[2]; uint2 rb[2]; float rs[2];

    auto LDG = [&](int kt) {
        const int k0 = kt << 5;
        {
            ra[0] = *(const uint4*)(A + (long long)(m0 + r0)*lda + (k0 + c0));
            size_t off = (size_t)(n0 + r0)*K + (k0 + c0);
            rb[0] = *(const uint2*)(Bq + off);
            rs[0] = Bamax[off >> 6];
        }
        {
            ra[1] = *(const uint4*)(A + (long long)(m0 + r1)*lda + (k0 + c1));
            size_t off = (size_t)(n0 + r1)*K + (k0 + c1);
            rb[1] = *(const uint2*)(Bq + off);
            rs[1] = Bamax[off >> 6];
        }
    };
    auto STS = [&](int buf) {
        #pragma unroll
        for (int i = 0; i < 2; i++) {
            const int r = i ? r1 : r0, c = i ? c1 : c0;
            *(uint4*)&sA[buf][r][c] = ra[i];
            const unsigned char* cb = (const unsigned char*)&rb[i];
            __half2 hv[4];
            #pragma unroll
            for (int j = 0; j < 4; j++)
                hv[j] = __floats2half2_rn(NF4[cb[2*j]]*rs[i], NF4[cb[2*j+1]]*rs[i]);
            *(uint4*)&sB[buf][r][c] = *(const uint4*)hv;
        }
    };

    LDG(0);
    STS(0);
    __syncthreads();

    for (int kt = 0; kt < NT; kt++) {
        const int cur = kt & 1;
        if (kt + 1 < NT) LDG(kt + 1);

        #pragma unroll
        for (int kk = 0; kk < 32; kk += 16) {
            wmma::fragment<wmma::matrix_a,16,16,16,__half,wmma::row_major> af[2];
            #pragma unroll
            for (int i = 0; i < 2; i++)
                wmma::load_matrix_sync(af[i], &sA[cur][wm*32 + i*16][kk], 48);
            #pragma unroll
            for (int j = 0; j < 4; j++) {
                wmma::fragment<wmma::matrix_b,16,16,16,__half,wmma::col_major> bf;
                wmma::load_matrix_sync(bf, &sB[cur][wn*64 + j*16][kk], 48);
                #pragma unroll
                for (int i = 0; i < 2; i++) wmma::mma_sync(acc[i][j], af[i], bf, acc[i][j]);
            }
        }

        if (kt + 1 < NT) {
            STS(cur ^ 1);
            __syncthreads();
        }
    }

    #pragma unroll
    for (int i = 0; i < 2; i++)
        #pragma unroll
        for (int j = 0; j < 4; j++) {
            float* cp = C + (long long)(m0 + wm*32 + i*16)*ldc + (n0 + wn*64 + j*16);
            if constexpr (ACC) {
                wmma::fragment<wmma::accumulator,16,16,16,float> cf;
                wmma::load_matrix_sync(cf, cp, ldc, wmma::mem_row_major);
                #pragma unroll
                for (int e = 0; e < cf.num_elements; e++) acc[i][j].x[e] += cf.x[e];
            }
            wmma::store_matrix_sync(cp, acc[i][j], ldc, wmma::mem_row_major);
        }
}

// ---------------- host launcher ----------------
#define CDIV(a,b) (((a)+(b)-1)/(b))

static void gemm_q(const __half* A, const unsigned char* Bq, const float* Bamax,
                   float* C, int M, int N, int K, bool accum) {
    dim3 g(N/128, M/128, 1);
    if (accum)
        gemm_qt<true ><<<g,256>>>(A, Bq, Bamax, C, K, K, N);
    else
        gemm_qt<false><<<g,256>>>(A, Bq, Bamax, C, K, K, N);
}

static void conv_idx(const void* src, size_t elem_off, unsigned char* dst, size_t n) {
    int n4 = (int)(n >> 2);
    conv_idx_k<<<CDIV(n4,256),256>>>(src, elem_off, dst, n4);
}

extern "C" void kernel_launch(void* const* d_in, const int* in_sizes, int n_in,
                              void* d_out, int out_size) {
    const int*   ids = (const int*)d_in[0];
    const int*   am  = (const int*)d_in[1];
    const float* emb = (const float*)d_in[2];
    const void*  qi  = d_in[3];
    const float* qa  = (const float*)d_in[4];
    const void*  ki  = d_in[5];
    const float* ka  = (const float*)d_in[6];
    const void*  vi  = d_in[7];
    const float* va  = (const float*)d_in[8];
    const void*  oi  = d_in[9];
    const float* oa  = (const float*)d_in[10];
    const void*  gi  = d_in[11];
    const float* ga  = (const float*)d_in[12];
    const void*  ui  = d_in[13];
    const float* ua  = (const float*)d_in[14];
    const void*  di  = d_in[15];
    const float* da  = (const float*)d_in[16];
    const float* ln1 = (const float*)d_in[17];
    const float* ln2 = (const float*)d_in[18];
    const float* lnf = (const float*)d_in[19];
    float* out = (float*)d_out;

    void *p_h,*p_x,*p_q,*p_k,*p_v,*p_qh,*p_kh,*p_vh,*p_sc,*p_pr,*p_ch,*p_act,*p_w8;
    cudaGetSymbolAddress(&p_h,  g_h);
    cudaGetSymbolAddress(&p_x,  g_x);
    cudaGetSymbolAddress(&p_q,  g_q);
    cudaGetSymbolAddress(&p_k,  g_k);
    cudaGetSymbolAddress(&p_v,  g_v);
    cudaGetSymbolAddress(&p_qh, g_qh);
    cudaGetSymbolAddress(&p_kh, g_kh);
    cudaGetSymbolAddress(&p_vh, g_vh);
    cudaGetSymbolAddress(&p_sc, g_scores);
    cudaGetSymbolAddress(&p_pr, g_probs);
    cudaGetSymbolAddress(&p_ch, g_ctxh);
    cudaGetSymbolAddress(&p_act,g_act);
    cudaGetSymbolAddress(&p_w8, g_wq8);

    __half* X    = (__half*)p_x;
    float*  Hst  = (float*)p_h;
    float*  Qf   = (float*)p_q;
    float*  Ctxf = (float*)p_q;            // alias: q (f32) dead after rope
    float*  Gf   = (float*)p_sc;           // alias: scores dead after ctx GEMM
    float*  Uf   = (float*)p_pr;           // alias: probs  dead after ctx GEMM
    unsigned char* Wc = (unsigned char*)p_w8;

    // ---- normalize NF4 code arrays to uint8 (handles u8/i32/f32 delivery) ----
    detect_k<<<1,32>>>(qi);
    for (int l = 0; l < Lc; l++) {
        size_t lb = (size_t)l * TLe;
        conv_idx(qi, (size_t)l*SQe,  Wc + lb + OQ, SQe);
        conv_idx(ki, (size_t)l*SKVe, Wc + lb + OK, SKVe);
        conv_idx(vi, (size_t)l*SKVe, Wc + lb + OV, SKVe);
        conv_idx(oi, (size_t)l*SQe,  Wc + lb + OO, SQe);
        conv_idx(gi, (size_t)l*SFe,  Wc + lb + OG, SFe);
        conv_idx(ui, (size_t)l*SFe,  Wc + lb + OU, SFe);
        conv_idx(di, (size_t)l*SFe,  Wc + lb + OD, SFe);
    }

    embed_k<<<CDIV(Mc*Dc/4,256),256>>>(ids, emb);
    rope_table_k<<<CDIV(Sc*64,256),256>>>();

    for (int l = 0; l < Lc; l++) {
        size_t lb = (size_t)l * TLe;
        // ---- attention ----
        rmsnorm_k<<<Mc,256>>>(Hst, ln1 + l*Dc, X);

        gemm_q(X, Wc + lb + OQ, qa + (size_t)l*(SQe/64),  Qf,          Mc, Dc,  Dc, false);
        gemm_q(X, Wc + lb + OK, ka + (size_t)l*(SKVe/64), (float*)p_k, Mc, KVc, Dc, false);
        gemm_q(X, Wc + lb + OV, va + (size_t)l*(SKVe/64), (float*)p_v, Mc, KVc, Dc, false);

        rope_q_k<<<CDIV(Mc*Hc*64,256),256>>>();
        rope_k_k<<<CDIV(Mc*Hc*64,256),256>>>();
        conv_v_k<<<CDIV(Mc*Dc,256),256>>>();

        // scores[b,h] = q @ k^T  (K=128), batched over 64 (b,h)
        gemm_tc<true,false><<<dim3(Sc/128, Sc/128, BHc),256>>>(
            (__half*)p_qh, (__half*)p_kh, (float*)p_sc, HDc, Dc, Dc, Sc,
            (long long)Sc*Dc, HDc, (long long)Sc*Dc, HDc,
            (long long)Hc*Sc*Sc, (long long)Sc*Sc, Hc);

        softmax_k<<<BHc*Sc,256>>>(am, (float*)p_sc, (__half*)p_pr);

        // ctx[b,h] = probs @ v   (N=128, K=S), batched over 64
        gemm_tc<false,false><<<dim3(HDc/128, Sc/128, BHc),256>>>(
            (__half*)p_pr, (__half*)p_vh, Ctxf, Sc, Sc, Dc, Dc,
            (long long)Hc*Sc*Sc, (long long)Sc*Sc, (long long)Sc*Dc, HDc,
            (long long)Sc*Dc, HDc, Hc);

        f2h_k<<<CDIV(Mc*Dc,256),256>>>(Ctxf, (__half*)p_ch, Mc*Dc);

        gemm_q((__half*)p_ch, Wc + lb + OO, oa + (size_t)l*(SQe/64), Hst, Mc, Dc, Dc, true);

        // ---- MLP ----
        rmsnorm_k<<<Mc,256>>>(Hst, ln2 + l*Dc, X);

        gemm_q(X, Wc + lb + OG, ga + (size_t)l*(SFe/64), Gf, Mc, Fc, Dc, false);
        gemm_q(X, Wc + lb + OU, ua + (size_t)l*(SFe/64), Uf, Mc, Fc, Dc, false);

        silu_k<<<CDIV(Mc*Fc,256),256>>>(Gf, Uf, (__half*)p_act, Mc*Fc);

        gemm_q((__half*)p_act, Wc + lb + OD, da + (size_t)l*(SFe/64), Hst, Mc, Dc, Fc, true);
    }

    rms_scale_k<<<Mc,256>>>(Hst);
    pool_k<<<CDIV(Bc*Dc,256),256>>>(am, lnf, out);
}

// round 10
// speedup vs baseline: 1.0255x; 1.0255x over previous
#include <cuda_runtime.h>
#include <cuda_fp16.h>
#include <mma.h>
#include <math.h>

using namespace nvcuda;

// ---------------- problem constants ----------------
#define Lc   2
#define Dc   4096
#define KVc  1024
#define Fc   14336
#define Hc   32
#define HKc  8
#define HDc  128
#define Bc   2
#define Sc   1024
#define Mc   (Bc*Sc)     // 2048 rows
#define BHc  (Bc*Hc)     // 64 attention batches
#define RMS_EPS 1e-5f

// idx array sizes (elements) per layer
#define SQe  (Dc*Dc)
#define SKVe (KVc*Dc)
#define SFe  (Fc*Dc)
#define TLe  (2*SQe + 2*SKVe + 3*SFe)
// canonical offsets within a layer
#define OQ 0
#define OK (SQe)
#define OV (SQe + SKVe)
#define OO (SQe + 2*SKVe)
#define OG (2*SQe + 2*SKVe)
#define OU (2*SQe + 2*SKVe + SFe)
#define OD (2*SQe + 2*SKVe + 2*SFe)

// ---------------- scratch (device globals; allocation-free) ----------------
__device__ float   g_h[Mc*Dc];
__device__ __half  g_x[Mc*Dc];
__device__ float   g_q[Mc*Dc];
__device__ float   g_k[Mc*KVc];
__device__ float   g_v[Mc*KVc];
__device__ __half  g_qh[Mc*Dc];
__device__ __half  g_kh[Mc*Dc];
__device__ __half  g_vh[Mc*Dc];
__device__ float   g_scores[(size_t)BHc*Sc*Sc];      // 268MB (alias: MLP gate f32)
__device__ __half  g_probs[(size_t)BHc*Sc*Sc];       // 134MB (alias: MLP up f32)
__device__ __half  g_ctxh[Mc*Dc];
__device__ __half  g_act[Mc*Fc];
__device__ float   g_cos[Sc*64];
__device__ float   g_sin[Sc*64];
__device__ float   g_rms[Mc];
__device__ unsigned char g_wq8[(size_t)Lc*TLe];      // canonical uint8 NF4 codes

__constant__ float NF4[16] = {
    -1.0f, -0.6961928009986877f, -0.5250730514526367f, -0.39491748809814453f,
    -0.28444138169288635f, -0.18477343022823334f, -0.09105003625154495f, 0.0f,
    0.07958029955625534f, 0.16093020141124725f, 0.24611230194568634f,
    0.33791524171829224f, 0.44070982933044434f, 0.5626170039176941f,
    0.7229568362236023f, 1.0f };

// ---------------- single-launch idx normalization (u8/i32/f32 -> u8) -------
__global__ void conv_all_k(const void* __restrict__ qi, const void* __restrict__ ki,
                           const void* __restrict__ vi, const void* __restrict__ oi,
                           const void* __restrict__ gi, const void* __restrict__ ui,
                           const void* __restrict__ di, unsigned char* __restrict__ dst) {
    __shared__ int smode;
    if (threadIdx.x == 0) {
        const unsigned int* w = (const unsigned int*)qi;
        bool i32 = true, f32 = true;
        for (int i = 0; i < 64; i++) {
            unsigned int v = w[i];
            if (v >= 16u) i32 = false;
            float f = __uint_as_float(v);
            if (!(f >= 0.f && f < 16.f && f == floorf(f))) f32 = false;
        }
        smode = i32 ? 1 : (f32 ? 2 : 0);
    }
    __syncthreads();
    const int mode = smode;
    long long t = (long long)blockIdx.x * 256 + threadIdx.x;   // uchar4 units
    const long long N4 = (long long)Lc * TLe / 4;
    if (t >= N4) return;
    long long l  = t / (TLe/4);
    long long re = (t - l*(TLe/4)) * 4;                        // elem within layer
    const void* src; long long selem;
    if      (re < OK) { src = qi; selem = l*SQe  + (re - OQ); }
    else if (re < OV) { src = ki; selem = l*SKVe + (re - OK); }
    else if (re < OO) { src = vi; selem = l*SKVe + (re - OV); }
    else if (re < OG) { src = oi; selem = l*SQe  + (re - OO); }
    else if (re < OU) { src = gi; selem = l*SFe  + (re - OG); }
    else if (re < OD) { src = ui; selem = l*SFe  + (re - OU); }
    else              { src = di; selem = l*SFe  + (re - OD); }
    long long s4 = selem >> 2;
    uchar4 o;
    if (mode == 0) {
        o = ((const uchar4*)src)[s4];
    } else if (mode == 1) {
        int4 v = ((const int4*)src)[s4];
        o = make_uchar4((unsigned char)v.x, (unsigned char)v.y,
                        (unsigned char)v.z, (unsigned char)v.w);
    } else {
        float4 v = ((const float4*)src)[s4];
        o = make_uchar4((unsigned char)(int)v.x, (unsigned char)(int)v.y,
                        (unsigned char)(int)v.z, (unsigned char)(int)v.w);
    }
    ((uchar4*)dst)[t] = o;
}

// ---------------- elementwise kernels ----------------
__global__ void embed_k(const int* __restrict__ ids, const float* __restrict__ emb) {
    int t = blockIdx.x * 256 + threadIdx.x;
    if (t >= Mc*Dc/4) return;
    int row = t / (Dc/4);
    int c4  = t % (Dc/4);
    ((float4*)g_h)[t] = ((const float4*)(emb + (size_t)ids[row]*Dc))[c4];
}

__global__ void rope_table_k() {
    int t = blockIdx.x * 256 + threadIdx.x;
    if (t >= Sc*64) return;
    int s = t >> 6, j = t & 63;
    double inv = pow(500000.0, -(double)(2*j) / 128.0);
    float ang = (float)s * (float)inv;
    g_cos[t] = cosf(ang);
    g_sin[t] = sinf(ang);
}

__global__ void rmsnorm_k(const float* __restrict__ src, const float* __restrict__ w,
                          __half* __restrict__ dst) {
    int row = blockIdx.x;
    const float* x = src + (size_t)row*Dc;
    __half* y = dst + (size_t)row*Dc;
    int tid = threadIdx.x;
    float s = 0.f;
    for (int d = tid*4; d < Dc; d += 1024) {
        float4 v = *(const float4*)(x + d);
        s += v.x*v.x + v.y*v.y + v.z*v.z + v.w*v.w;
    }
    __shared__ float red[256];
    red[tid] = s; __syncthreads();
    for (int o = 128; o > 0; o >>= 1) { if (tid < o) red[tid] += red[tid+o]; __syncthreads(); }
    float r = rsqrtf(red[0] / (float)Dc + RMS_EPS);
    for (int d = tid; d < Dc; d += 256) y[d] = __float2half(x[d] * r * w[d]);
}

__global__ void rms_scale_k(const float* __restrict__ src) {
    int row = blockIdx.x;
    const float* x = src + (size_t)row*Dc;
    int tid = threadIdx.x;
    float s = 0.f;
    for (int d = tid*4; d < Dc; d += 1024) {
        float4 v = *(const float4*)(x + d);
        s += v.x*v.x + v.y*v.y + v.z*v.z + v.w*v.w;
    }
    __shared__ float red[256];
    red[tid] = s; __syncthreads();
    for (int o = 128; o > 0; o >>= 1) { if (tid < o) red[tid] += red[tid+o]; __syncthreads(); }
    if (tid == 0) g_rms[row] = rsqrtf(red[0] / (float)Dc + RMS_EPS);
}

__global__ void rope_q_k() {
    int t = blockIdx.x * 256 + threadIdx.x;
    if (t >= Mc*Hc*64) return;
    int j  = t & 63;
    int bh = t >> 6;
    int hh = bh % Hc;
    int bs = bh / Hc;
    int s  = bs % Sc;
    size_t base = (size_t)bs*Dc + (size_t)hh*HDc;
    float x1 = g_q[base + j], x2 = g_q[base + 64 + j];
    float c = g_cos[s*64 + j], sn = g_sin[s*64 + j];
    g_qh[base + j]      = __float2half(x1*c - x2*sn);
    g_qh[base + 64 + j] = __float2half(x2*c + x1*sn);
}

__global__ void rope_k_k() {
    int t = blockIdx.x * 256 + threadIdx.x;
    if (t >= Mc*Hc*64) return;
    int j  = t & 63;
    int bh = t >> 6;
    int hh = bh % Hc;
    int bs = bh / Hc;
    int s  = bs % Sc;
    size_t src = (size_t)bs*KVc + (size_t)(hh >> 2)*HDc;
    size_t dst = (size_t)bs*Dc  + (size_t)hh*HDc;
    float x1 = g_k[src + j], x2 = g_k[src + 64 + j];
    float c = g_cos[s*64 + j], sn = g_sin[s*64 + j];
    g_kh[dst + j]      = __float2half(x1*c - x2*sn);
    g_kh[dst + 64 + j] = __float2half(x2*c + x1*sn);
}

__global__ void conv_v_k() {
    int t = blockIdx.x * 256 + threadIdx.x;
    if (t >= Mc*Dc) return;
    int d    = t & 127;
    int rest = t >> 7;
    int hh   = rest % Hc;
    int bs   = rest / Hc;
    g_vh[t] = __float2half(g_v[(size_t)bs*KVc + (size_t)(hh >> 2)*HDc + d]);
}

__global__ void f2h_k(const float* __restrict__ src, __half* __restrict__ dst, int n) {
    int t = blockIdx.x * 256 + threadIdx.x;
    if (t < n) dst[t] = __float2half(src[t]);
}

__global__ void silu_k(const float* __restrict__ g, const float* __restrict__ u,
                       __half* __restrict__ act, int n) {
    int t = blockIdx.x * 256 + threadIdx.x;
    if (t >= n) return;
    float gv = g[t];
    act[t] = __float2half(gv / (1.f + __expf(-gv)) * u[t]);
}

__global__ void softmax_k(const int* __restrict__ am,
                          const float* __restrict__ scores, __half* __restrict__ probs) {
    const int z  = blockIdx.x;
    const int i  = z % Sc;
    const int bh = z / Sc;
    const int b  = bh / Hc;
    const float* row = scores + (size_t)bh*Sc*Sc + (size_t)i*Sc;
    __half* prow     = probs  + (size_t)bh*Sc*Sc + (size_t)i*Sc;
    const int tid = threadIdx.x;
    const float scale = 0.08838834764831845f;
    __shared__ float red[256];
    float mx = -3.4e38f;
    for (int j = tid; j < Sc; j += 256) {
        bool valid = (j <= i) && (am[b*Sc + j] > 0);
        if (valid) mx = fmaxf(mx, row[j] * scale);
    }
    red[tid] = mx; __syncthreads();
    for (int o = 128; o > 0; o >>= 1) { if (tid < o) red[tid] = fmaxf(red[tid], red[tid+o]); __syncthreads(); }
    mx = red[0]; __syncthreads();
    float sum = 0.f;
    for (int j = tid; j < Sc; j += 256) {
        bool valid = (j <= i) && (am[b*Sc + j] > 0);
        if (valid) sum += __expf(row[j] * scale - mx);
    }
    red[tid] = sum; __syncthreads();
    for (int o = 128; o > 0; o >>= 1) { if (tid < o) red[tid] += red[tid+o]; __syncthreads(); }
    float inv = 1.f / red[0];
    for (int j = tid; j < Sc; j += 256) {
        bool valid = (j <= i) && (am[b*Sc + j] > 0);
        float e = valid ? __expf(row[j] * scale - mx) * inv : 0.f;
        prow[j] = __float2half(e);
    }
}

__global__ void pool_k(const int* __restrict__ am, const float* __restrict__ w,
                       float* __restrict__ out) {
    int t = blockIdx.x * 256 + threadIdx.x;
    if (t >= Bc*Dc) return;
    int b = t / Dc, d = t % Dc;
    float acc = 0.f, cnt = 0.f;
    #pragma unroll 4
    for (int s = 0; s < Sc; s++) {
        float m = (float)am[b*Sc + s];
        acc += g_h[((size_t)(b*Sc + s))*Dc + d] * g_rms[b*Sc + s] * m;
        cnt += m;
    }
    out[t] = acc * w[d] / fmaxf(cnt, 1e-9f);
}

// ---------------- tensor-core GEMM (fp16 B operand; attention path) ----------
template<bool BT, bool ACC>
__global__ void __launch_bounds__(256) gemm_tc(
    const __half* __restrict__ A, const __half* __restrict__ B, float* __restrict__ C,
    int K, int lda, int ldb, int ldc,
    long long a1, long long a2, long long b1, long long b2,
    long long c1, long long c2, int zdiv)
{
    const int z = blockIdx.z;
    const long long zq = z / zdiv, zr = z % zdiv;
    A += zq*a1 + zr*a2;
    B += zq*b1 + zr*b2;
    C += zq*c1 + zr*c2;
    const int m0 = blockIdx.y * 128, n0 = blockIdx.x * 128;

    __shared__ __half sA[128][48];
    constexpr int SBR = BT ? 128 : 32;
    constexpr int SBC = BT ? 48 : 136;
    __shared__ __half sB[SBR][SBC];

    const int tid  = threadIdx.x;
    const int warp = tid >> 5;
    const int wm   = warp & 3;
    const int wn   = warp >> 2;

    wmma::fragment<wmma::accumulator,16,16,16,float> acc[2][4];
    #pragma unroll
    for (int i = 0; i < 2; i++)
        #pragma unroll
        for (int j = 0; j < 4; j++) wmma::fill_fragment(acc[i][j], 0.f);

    for (int k0 = 0; k0 < K; k0 += 32) {
        #pragma unroll
        for (int i = 0; i < 2; i++) {
            int v = tid + i*256;
            int r = v >> 2, c = (v & 3) * 8;
            *(uint4*)&sA[r][c] = *(const uint4*)(A + (long long)(m0 + r)*lda + (k0 + c));
        }
        if constexpr (BT) {
            #pragma unroll
            for (int i = 0; i < 2; i++) {
                int v = tid + i*256;
                int r = v >> 2, c = (v & 3) * 8;
                *(uint4*)&sB[r][c] = *(const uint4*)(B + (long long)(n0 + r)*ldb + (k0 + c));
            }
        } else {
            #pragma unroll
            for (int i = 0; i < 2; i++) {
                int v = tid + i*256;
                int r = v >> 4, c = (v & 15) * 8;
                *(uint4*)&sB[r][c] = *(const uint4*)(B + (long long)(k0 + r)*ldb + (n0 + c));
            }
        }
        __syncthreads();

        #pragma unroll
        for (int kk = 0; kk < 32; kk += 16) {
            wmma::fragment<wmma::matrix_a,16,16,16,__half,wmma::row_major> af[2];
            #pragma unroll
            for (int i = 0; i < 2; i++)
                wmma::load_matrix_sync(af[i], &sA[wm*32 + i*16][kk], 48);
            if constexpr (BT) {
                #pragma unroll
                for (int j = 0; j < 4; j++) {
                    wmma::fragment<wmma::matrix_b,16,16,16,__half,wmma::col_major> bf;
                    wmma::load_matrix_sync(bf, &sB[wn*64 + j*16][kk], 48);
                    #pragma unroll
                    for (int i = 0; i < 2; i++) wmma::mma_sync(acc[i][j], af[i], bf, acc[i][j]);
                }
            } else {
                #pragma unroll
                for (int j = 0; j < 4; j++) {
                    wmma::fragment<wmma::matrix_b,16,16,16,__half,wmma::row_major> bf;
                    wmma::load_matrix_sync(bf, &sB[kk][wn*64 + j*16], 136);
                    #pragma unroll
                    for (int i = 0; i < 2; i++) wmma::mma_sync(acc[i][j], af[i], bf, acc[i][j]);
                }
            }
        }
        __syncthreads();
    }

    #pragma unroll
    for (int i = 0; i < 2; i++)
        #pragma unroll
        for (int j = 0; j < 4; j++) {
            float* cp = C + (long long)(m0 + wm*32 + i*16)*ldc + (n0 + wn*64 + j*16);
            if constexpr (ACC) {
                wmma::fragment<wmma::accumulator,16,16,16,float> cf;
                wmma::load_matrix_sync(cf, cp, ldc, wmma::mem_row_major);
                #pragma unroll
                for (int e = 0; e < cf.num_elements; e++) acc[i][j].x[e] += cf.x[e];
            }
            wmma::store_matrix_sync(cp, acc[i][j], ldc, wmma::mem_row_major);
        }
}

// ---------------- fused NF4-dequant tensor-core GEMM (projection path) ------
// 128x128 CTA tile, 4 warps of 64x64, double-buffered, smem stride 40
// (80B rows -> all 8 consecutive row-starts hit distinct banks: LDSM
// conflict-free; 48-stride had 2-way conflicts). LDSM:HMMA ratio 0.5.
// Numerically identical to standalone dequant (fp32 NF4[c]*amax -> half).
template<bool ACC>
__global__ void __launch_bounds__(128) gemm_qt(
    const __half* __restrict__ A,
    const unsigned char* __restrict__ Bq,
    const float* __restrict__ Bamax,
    float* __restrict__ C,
    int K, int lda, int ldc)
{
    const int m0 = blockIdx.y * 128, n0 = blockIdx.x * 128;

    __shared__ __half sA[2][128][40];
    __shared__ __half sB[2][128][40];

    const int tid  = threadIdx.x;
    const int warp = tid >> 5;
    const int wm   = warp & 1;          // 2 warps along M
    const int wn   = warp >> 1;         // 2 warps along N

    // per-thread chunk coords: 4 chunks of 8 elems over a 128x32 tile
    int rr[4], cc[4];
    #pragma unroll
    for (int i = 0; i < 4; i++) {
        int v = tid + i*128;
        rr[i] = v >> 2;
        cc[i] = (v & 3) * 8;
    }

    wmma::fragment<wmma::accumulator,16,16,16,float> acc[4][4];
    #pragma unroll
    for (int i = 0; i < 4; i++)
        #pragma unroll
        for (int j = 0; j < 4; j++) wmma::fill_fragment(acc[i][j], 0.f);

    const int NT = K >> 5;
    uint4 ra[4]; uint2 rb[4]; float rs[4];

    auto LDG = [&](int kt) {
        const int k0 = kt << 5;
        #pragma unroll
        for (int i = 0; i < 4; i++) {
            ra[i] = *(const uint4*)(A + (long long)(m0 + rr[i])*lda + (k0 + cc[i]));
            size_t off = (size_t)(n0 + rr[i])*K + (k0 + cc[i]);
            rb[i] = *(const uint2*)(Bq + off);
            rs[i] = Bamax[off >> 6];
        }
    };
    auto STS = [&](int buf) {
        #pragma unroll
        for (int i = 0; i < 4; i++) {
            *(uint4*)&sA[buf][rr[i]][cc[i]] = ra[i];
            const unsigned char* cb = (const unsigned char*)&rb[i];
            __half2 hv[4];
            #pragma unroll
            for (int j = 0; j < 4; j++)
                hv[j] = __floats2half2_rn(NF4[cb[2*j]]*rs[i], NF4[cb[2*j+1]]*rs[i]);
            *(uint4*)&sB[buf][rr[i]][cc[i]] = *(const uint4*)hv;
        }
    };

    LDG(0);
    STS(0);
    __syncthreads();

    for (int kt = 0; kt < NT; kt++) {
        const int cur = kt & 1;
        if (kt + 1 < NT) LDG(kt + 1);      // overlap GMEM with MMAs

        #pragma unroll
        for (int kk = 0; kk < 32; kk += 16) {
            wmma::fragment<wmma::matrix_a,16,16,16,__half,wmma::row_major> af[4];
            wmma::fragment<wmma::matrix_b,16,16,16,__half,wmma::col_major> bf[4];
            #pragma unroll
            for (int i = 0; i < 4; i++)
                wmma::load_matrix_sync(af[i], &sA[cur][wm*64 + i*16][kk], 40);
            #pragma unroll
            for (int j = 0; j < 4; j++)
                wmma::load_matrix_sync(bf[j], &sB[cur][wn*64 + j*16][kk], 40);
            #pragma unroll
            for (int j = 0; j < 4; j++)
                #pragma unroll
                for (int i = 0; i < 4; i++)
                    wmma::mma_sync(acc[i][j], af[i], bf[j], acc[i][j]);
        }

        if (kt + 1 < NT) {
            STS(cur ^ 1);                  // other buffer: safe vs readers of cur
            __syncthreads();               // publish + retire readers of cur
        }
    }

    #pragma unroll
    for (int i = 0; i < 4; i++)
        #pragma unroll
        for (int j = 0; j < 4; j++) {
            float* cp = C + (long long)(m0 + wm*64 + i*16)*ldc + (n0 + wn*64 + j*16);
            if constexpr (ACC) {
                wmma::fragment<wmma::accumulator,16,16,16,float> cf;
                wmma::load_matrix_sync(cf, cp, ldc, wmma::mem_row_major);
                #pragma unroll
                for (int e = 0; e < cf.num_elements; e++) acc[i][j].x[e] += cf.x[e];
            }
            wmma::store_matrix_sync(cp, acc[i][j], ldc, wmma::mem_row_major);
        }
}

// ---------------- host launcher ----------------
#define CDIV(a,b) (((a)+(b)-1)/(b))

static void gemm_q(const __half* A, const unsigned char* Bq, const float* Bamax,
                   float* C, int M, int N, int K, bool accum) {
    dim3 g(N/128, M/128, 1);
    if (accum)
        gemm_qt<true ><<<g,128>>>(A, Bq, Bamax, C, K, K, N);
    else
        gemm_qt<false><<<g,128>>>(A, Bq, Bamax, C, K, K, N);
}

extern "C" void kernel_launch(void* const* d_in, const int* in_sizes, int n_in,
                              void* d_out, int out_size) {
    const int*   ids = (const int*)d_in[0];
    const int*   am  = (const int*)d_in[1];
    const float* emb = (const float*)d_in[2];
    const void*  qi  = d_in[3];
    const float* qa  = (const float*)d_in[4];
    const void*  ki  = d_in[5];
    const float* ka  = (const float*)d_in[6];
    const void*  vi  = d_in[7];
    const float* va  = (const float*)d_in[8];
    const void*  oi  = d_in[9];
    const float* oa  = (const float*)d_in[10];
    const void*  gi  = d_in[11];
    const float* ga  = (const float*)d_in[12];
    const void*  ui  = d_in[13];
    const float* ua  = (const float*)d_in[14];
    const void*  di  = d_in[15];
    const float* da  = (const float*)d_in[16];
    const float* ln1 = (const float*)d_in[17];
    const float* ln2 = (const float*)d_in[18];
    const float* lnf = (const float*)d_in[19];
    float* out = (float*)d_out;

    void *p_h,*p_x,*p_q,*p_k,*p_v,*p_qh,*p_kh,*p_vh,*p_sc,*p_pr,*p_ch,*p_act,*p_w8;
    cudaGetSymbolAddress(&p_h,  g_h);
    cudaGetSymbolAddress(&p_x,  g_x);
    cudaGetSymbolAddress(&p_q,  g_q);
    cudaGetSymbolAddress(&p_k,  g_k);
    cudaGetSymbolAddress(&p_v,  g_v);
    cudaGetSymbolAddress(&p_qh, g_qh);
    cudaGetSymbolAddress(&p_kh, g_kh);
    cudaGetSymbolAddress(&p_vh, g_vh);
    cudaGetSymbolAddress(&p_sc, g_scores);
    cudaGetSymbolAddress(&p_pr, g_probs);
    cudaGetSymbolAddress(&p_ch, g_ctxh);
    cudaGetSymbolAddress(&p_act,g_act);
    cudaGetSymbolAddress(&p_w8, g_wq8);

    __half* X    = (__half*)p_x;
    float*  Hst  = (float*)p_h;
    float*  Qf   = (float*)p_q;
    float*  Ctxf = (float*)p_q;
    float*  Gf   = (float*)p_sc;
    float*  Uf   = (float*)p_pr;
    unsigned char* Wc = (unsigned char*)p_w8;

    // launch 1: normalize all NF4 code arrays to canonical uint8
    {
        long long n4 = (long long)Lc * TLe / 4;
        conv_all_k<<<(unsigned)CDIV(n4,256),256>>>(qi, ki, vi, oi, gi, ui, di, Wc);
    }
    embed_k<<<CDIV(Mc*Dc/4,256),256>>>(ids, emb);        // launch 2
    rope_table_k<<<CDIV(Sc*64,256),256>>>();             // launch 3

    for (int l = 0; l < Lc; l++) {
        size_t lb = (size_t)l * TLe;
        // ---- attention ----
        rmsnorm_k<<<Mc,256>>>(Hst, ln1 + l*Dc, X);       // launch 4 (l=0)

        // launch 5 (l=0): Q projection — ncu -s 5 profiles this GEMM
        gemm_q(X, Wc + lb + OQ, qa + (size_t)l*(SQe/64),  Qf,          Mc, Dc,  Dc, false);
        gemm_q(X, Wc + lb + OK, ka + (size_t)l*(SKVe/64), (float*)p_k, Mc, KVc, Dc, false);
        gemm_q(X, Wc + lb + OV, va + (size_t)l*(SKVe/64), (float*)p_v, Mc, KVc, Dc, false);

        rope_q_k<<<CDIV(Mc*Hc*64,256),256>>>();
        rope_k_k<<<CDIV(Mc*Hc*64,256),256>>>();
        conv_v_k<<<CDIV(Mc*Dc,256),256>>>();

        gemm_tc<true,false><<<dim3(Sc/128, Sc/128, BHc),256>>>(
            (__half*)p_qh, (__half*)p_kh, (float*)p_sc, HDc, Dc, Dc, Sc,
            (long long)Sc*Dc, HDc, (long long)Sc*Dc, HDc,
            (long long)Hc*Sc*Sc, (long long)Sc*Sc, Hc);

        softmax_k<<<BHc*Sc,256>>>(am, (float*)p_sc, (__half*)p_pr);

        gemm_tc<false,false><<<dim3(HDc/128, Sc/128, BHc),256>>>(
            (__half*)p_pr, (__half*)p_vh, Ctxf, Sc, Sc, Dc, Dc,
            (long long)Hc*Sc*Sc, (long long)Sc*Sc, (long long)Sc*Dc, HDc,
            (long long)Sc*Dc, HDc, Hc);

        f2h_k<<<CDIV(Mc*Dc,256),256>>>(Ctxf, (__half*)p_ch, Mc*Dc);

        gemm_q((__half*)p_ch, Wc + lb + OO, oa + (size_t)l*(SQe/64), Hst, Mc, Dc, Dc, true);

        // ---- MLP ----
        rmsnorm_k<<<Mc,256>>>(Hst, ln2 + l*Dc, X);

        gemm_q(X, Wc + lb + OG, ga + (size_t)l*(SFe/64), Gf, Mc, Fc, Dc, false);
        gemm_q(X, Wc + lb + OU, ua + (size_t)l*(SFe/64), Uf, Mc, Fc, Dc, false);

        silu_k<<<CDIV(Mc*Fc,256),256>>>(Gf, Uf, (__half*)p_act, Mc*Fc);

        gemm_q((__half*)p_act, Wc + lb + OD, da + (size_t)l*(SFe/64), Hst, Mc, Dc, Fc, true);
    }

    rms_scale_k<<<Mc,256>>>(Hst);
    pool_k<<<CDIV(Bc*Dc,256),256>>>(am, lnf, out);
}